// round 1
// baseline (speedup 1.0000x reference)
#include <cuda_runtime.h>
#include <cuda_bf16.h>

// ----------------------------------------------------------------------------
// AdaptiveMetaLearnerV2: theta[b,p] = F(x[b,p]), qt[b] = mean_p G(x[b,p])
// where F,G are scalar functions (per-coordinate MLP+2xLSTM-step from zero
// state). Strategy: tabulate F,G on a fine grid (kernel 1), then do a
// memory-bound interpolating lookup over the 2.1M elements (kernel 2), and a
// deterministic final reduction for qt (kernel 3).
// ----------------------------------------------------------------------------

#define H 20
#define NL 2
#define TAB_N 32768              // knots span [-16, 16], h = 2^-10
#define X_MIN (-16.0f)
#define INV_H 1024.0f
#define B_DIM 64
#define P_DIM 32768
#define CHUNKS 16                // blocks per batch row in kernel 2
#define K2_THREADS 256
#define K2_VECS 2                // float4 loads per thread (8 elems/thread)

__device__ float2 g_table[TAB_N + 1];
__device__ float  g_partial[B_DIM * CHUNKS];

__device__ __forceinline__ float fast_sigmoid(float z) {
    return __fdividef(1.0f, 1.0f + __expf(-z));
}
__device__ __forceinline__ float fast_tanh(float z) {
    // 2*sigmoid(2z)-1; saturates correctly for |z| large.
    return __fdividef(2.0f, 1.0f + __expf(-2.0f * z)) - 1.0f;
}

// ----------------------------------------------------------------------------
// Kernel 1: build the table. One thread per knot. Weights staged in smem.
// Gate rows: i = rows [0,20), f = [20,40) (UNUSED: f*c0 = 0), g = [40,60),
// o = [60,80). We pack the 60 used rows as q in [0,60): r = q<20 ? q : q+20.
// ----------------------------------------------------------------------------
__global__ void build_table_kernel(
    const float* __restrict__ W1,   const float* __restrict__ b1,
    const float* __restrict__ W_ih, const float* __restrict__ b_ih,
    const float* __restrict__ b_hh,
    const float* __restrict__ W_out, const float* __restrict__ b_out,
    const float* __restrict__ W_act, const float* __restrict__ b_act)
{
    __shared__ float sWi[NL][60][H];   // 2400 floats
    __shared__ float sbias[NL][60];    // b_ih + b_hh (h0 = 0, biases remain)
    __shared__ float sW1[H], sb1[H], sWo[H], sWa[H];

    for (int idx = threadIdx.x; idx < NL * 60 * H; idx += blockDim.x) {
        int l = idx / (60 * H);
        int rem = idx % (60 * H);
        int q = rem / H, h = rem % H;
        int r = (q < 20) ? q : q + 20;
        sWi[l][q][h] = W_ih[l * 4 * H * H + r * H + h];
    }
    for (int idx = threadIdx.x; idx < NL * 60; idx += blockDim.x) {
        int l = idx / 60, q = idx % 60;
        int r = (q < 20) ? q : q + 20;
        sbias[l][q] = b_ih[l * 4 * H + r] + b_hh[l * 4 * H + r];
    }
    if (threadIdx.x < H) {
        sW1[threadIdx.x] = W1[threadIdx.x];   // W1 is [H,1]
        sb1[threadIdx.x] = b1[threadIdx.x];
        sWo[threadIdx.x] = W_out[threadIdx.x];
        sWa[threadIdx.x] = W_act[threadIdx.x];
    }
    __syncthreads();

    int j = blockIdx.x * blockDim.x + threadIdx.x;
    if (j > TAB_N) return;

    float xv = X_MIN + (float)j * (1.0f / INV_H);

    float inp[H];
#pragma unroll
    for (int h = 0; h < H; h++) inp[h] = fmaf(xv, sW1[h], sb1[h]);

    for (int l = 0; l < NL; l++) {
        float nxt[H];
#pragma unroll
        for (int hh = 0; hh < H; hh++) {
            float ai = sbias[l][hh];
            float ag = sbias[l][hh + 20];
            float ao = sbias[l][hh + 40];
#pragma unroll
            for (int h2 = 0; h2 < H; h2++) {
                float v = inp[h2];
                ai = fmaf(v, sWi[l][hh][h2],      ai);
                ag = fmaf(v, sWi[l][hh + 20][h2], ag);
                ao = fmaf(v, sWi[l][hh + 40][h2], ao);
            }
            float iv = fast_sigmoid(ai);
            float gv = fast_tanh(ag);
            float ov = fast_sigmoid(ao);
            nxt[hh] = ov * fast_tanh(iv * gv);   // c = i*g (f*c0 = 0)
        }
#pragma unroll
        for (int h = 0; h < H; h++) inp[h] = nxt[h];
    }

    float F = b_out[0];
    float G = b_act[0];
#pragma unroll
    for (int h = 0; h < H; h++) {
        F = fmaf(inp[h], sWo[h], F);
        G = fmaf(inp[h], sWa[h], G);
    }
    g_table[j] = make_float2(F, G);
}

// ----------------------------------------------------------------------------
// Kernel 2: interpolating lookup + deterministic per-chunk act reduction.
// Grid: B_DIM * CHUNKS blocks, each covering 2048 contiguous elements of one
// batch row (so partial sums are per-row, fixed tree -> deterministic).
// ----------------------------------------------------------------------------
__device__ __forceinline__ void lut_eval(float xv, float& th, float& acc) {
    float t = fmaf(xv, INV_H, -X_MIN * INV_H);     // (x - X_MIN) * 1024
    int j = (int)t;                                // t >= 0 -> trunc == floor
    j = min(max(j, 0), TAB_N - 1);
    float fr = t - (float)j;
    float2 k0 = __ldg(&g_table[j]);
    float2 k1 = __ldg(&g_table[j + 1]);
    th = fmaf(fr, k1.x - k0.x, k0.x);
    acc += fmaf(fr, k1.y - k0.y, k0.y);
}

__global__ void __launch_bounds__(K2_THREADS)
lookup_kernel(const float* __restrict__ x, float* __restrict__ out)
{
    const int bidx  = blockIdx.x;
    const int row   = bidx / CHUNKS;
    const int chunk = bidx % CHUNKS;
    const int base4 = (row * P_DIM + chunk * (P_DIM / CHUNKS)) >> 2;

    const float4* x4 = reinterpret_cast<const float4*>(x) + base4;
    float4*       o4 = reinterpret_cast<float4*>(out) + base4;

    float acc = 0.0f;
#pragma unroll
    for (int k = 0; k < K2_VECS; k++) {
        int vi = threadIdx.x + k * K2_THREADS;
        float4 xv = x4[vi];
        float4 th;
        lut_eval(xv.x, th.x, acc);
        lut_eval(xv.y, th.y, acc);
        lut_eval(xv.z, th.z, acc);
        lut_eval(xv.w, th.w, acc);
        o4[vi] = th;
    }

    // deterministic intra-block reduction of act
#pragma unroll
    for (int off = 16; off > 0; off >>= 1)
        acc += __shfl_down_sync(0xffffffffu, acc, off);

    __shared__ float ws[K2_THREADS / 32];
    if ((threadIdx.x & 31) == 0) ws[threadIdx.x >> 5] = acc;
    __syncthreads();
    if (threadIdx.x == 0) {
        float s = 0.0f;
#pragma unroll
        for (int w = 0; w < K2_THREADS / 32; w++) s += ws[w];
        g_partial[bidx] = s;
    }
}

// ----------------------------------------------------------------------------
// Kernel 3: qt[b] = (sum of CHUNKS partials) / P
// ----------------------------------------------------------------------------
__global__ void finalize_kernel(float* __restrict__ out)
{
    int b = threadIdx.x;
    if (b >= B_DIM) return;
    float s = 0.0f;
#pragma unroll
    for (int c = 0; c < CHUNKS; c++) s += g_partial[b * CHUNKS + c];
    out[B_DIM * P_DIM + b] = s * (1.0f / (float)P_DIM);
}

// ----------------------------------------------------------------------------
extern "C" void kernel_launch(void* const* d_in, const int* in_sizes, int n_in,
                              void* d_out, int out_size)
{
    const float* x     = (const float*)d_in[0];
    const float* W1    = (const float*)d_in[1];
    const float* b1    = (const float*)d_in[2];
    const float* W_ih  = (const float*)d_in[3];
    const float* b_ih  = (const float*)d_in[4];
    // d_in[5] = W_hh (unused: h0 = 0)
    const float* b_hh  = (const float*)d_in[6];
    const float* W_out = (const float*)d_in[7];
    const float* b_out = (const float*)d_in[8];
    const float* W_act = (const float*)d_in[9];
    const float* b_act = (const float*)d_in[10];

    float* out = (float*)d_out;

    build_table_kernel<<<(TAB_N + 1 + 255) / 256, 256>>>(
        W1, b1, W_ih, b_ih, b_hh, W_out, b_out, W_act, b_act);

    lookup_kernel<<<B_DIM * CHUNKS, K2_THREADS>>>(x, out);

    finalize_kernel<<<1, B_DIM>>>(out);
}

// round 2
// speedup vs baseline: 1.0025x; 1.0025x over previous
#include <cuda_runtime.h>
#include <cuda_bf16.h>

// ----------------------------------------------------------------------------
// AdaptiveMetaLearnerV2: theta[b,p] = F(x[b,p]), qt[b] = mean_p G(x[b,p])
// where F,G are scalar functions (per-coordinate MLP+2xLSTM-step from zero
// state). Strategy: tabulate F,G on a fine grid (kernel 1), then do a
// memory-bound interpolating lookup over the 2.1M elements (kernel 2), and a
// deterministic final reduction for qt (kernel 3).
// ----------------------------------------------------------------------------

#define H 20
#define NL 2
#define TAB_N 32768              // knots span [-16, 16], h = 2^-10
#define X_MIN (-16.0f)
#define INV_H 1024.0f
#define B_DIM 64
#define P_DIM 32768
#define CHUNKS 16                // blocks per batch row in kernel 2
#define K2_THREADS 256
#define K2_VECS 2                // float4 loads per thread (8 elems/thread)

__device__ float2 g_table[TAB_N + 1];
__device__ float  g_partial[B_DIM * CHUNKS];

__device__ __forceinline__ float fast_sigmoid(float z) {
    return __fdividef(1.0f, 1.0f + __expf(-z));
}
__device__ __forceinline__ float fast_tanh(float z) {
    // 2*sigmoid(2z)-1; saturates correctly for |z| large.
    return __fdividef(2.0f, 1.0f + __expf(-2.0f * z)) - 1.0f;
}

// ----------------------------------------------------------------------------
// Kernel 1: build the table. One thread per knot. Weights staged in smem.
// Gate rows: i = rows [0,20), f = [20,40) (UNUSED: f*c0 = 0), g = [40,60),
// o = [60,80). We pack the 60 used rows as q in [0,60): r = q<20 ? q : q+20.
// ----------------------------------------------------------------------------
__global__ void build_table_kernel(
    const float* __restrict__ W1,   const float* __restrict__ b1,
    const float* __restrict__ W_ih, const float* __restrict__ b_ih,
    const float* __restrict__ b_hh,
    const float* __restrict__ W_out, const float* __restrict__ b_out,
    const float* __restrict__ W_act, const float* __restrict__ b_act)
{
    __shared__ float sWi[NL][60][H];   // 2400 floats
    __shared__ float sbias[NL][60];    // b_ih + b_hh (h0 = 0, biases remain)
    __shared__ float sW1[H], sb1[H], sWo[H], sWa[H];

    for (int idx = threadIdx.x; idx < NL * 60 * H; idx += blockDim.x) {
        int l = idx / (60 * H);
        int rem = idx % (60 * H);
        int q = rem / H, h = rem % H;
        int r = (q < 20) ? q : q + 20;
        sWi[l][q][h] = W_ih[l * 4 * H * H + r * H + h];
    }
    for (int idx = threadIdx.x; idx < NL * 60; idx += blockDim.x) {
        int l = idx / 60, q = idx % 60;
        int r = (q < 20) ? q : q + 20;
        sbias[l][q] = b_ih[l * 4 * H + r] + b_hh[l * 4 * H + r];
    }
    if (threadIdx.x < H) {
        sW1[threadIdx.x] = W1[threadIdx.x];   // W1 is [H,1]
        sb1[threadIdx.x] = b1[threadIdx.x];
        sWo[threadIdx.x] = W_out[threadIdx.x];
        sWa[threadIdx.x] = W_act[threadIdx.x];
    }
    __syncthreads();

    int j = blockIdx.x * blockDim.x + threadIdx.x;
    if (j > TAB_N) return;

    float xv = X_MIN + (float)j * (1.0f / INV_H);

    float inp[H];
#pragma unroll
    for (int h = 0; h < H; h++) inp[h] = fmaf(xv, sW1[h], sb1[h]);

    for (int l = 0; l < NL; l++) {
        float nxt[H];
#pragma unroll
        for (int hh = 0; hh < H; hh++) {
            float ai = sbias[l][hh];
            float ag = sbias[l][hh + 20];
            float ao = sbias[l][hh + 40];
#pragma unroll
            for (int h2 = 0; h2 < H; h2++) {
                float v = inp[h2];
                ai = fmaf(v, sWi[l][hh][h2],      ai);
                ag = fmaf(v, sWi[l][hh + 20][h2], ag);
                ao = fmaf(v, sWi[l][hh + 40][h2], ao);
            }
            float iv = fast_sigmoid(ai);
            float gv = fast_tanh(ag);
            float ov = fast_sigmoid(ao);
            nxt[hh] = ov * fast_tanh(iv * gv);   // c = i*g (f*c0 = 0)
        }
#pragma unroll
        for (int h = 0; h < H; h++) inp[h] = nxt[h];
    }

    float F = b_out[0];
    float G = b_act[0];
#pragma unroll
    for (int h = 0; h < H; h++) {
        F = fmaf(inp[h], sWo[h], F);
        G = fmaf(inp[h], sWa[h], G);
    }
    g_table[j] = make_float2(F, G);
}

// ----------------------------------------------------------------------------
// Kernel 2: interpolating lookup + deterministic per-chunk act reduction.
// Grid: B_DIM * CHUNKS blocks, each covering 2048 contiguous elements of one
// batch row (so partial sums are per-row, fixed tree -> deterministic).
// ----------------------------------------------------------------------------
__device__ __forceinline__ void lut_eval(float xv, float& th, float& acc) {
    float t = fmaf(xv, INV_H, -X_MIN * INV_H);     // (x - X_MIN) * 1024
    int j = (int)t;                                // t >= 0 -> trunc == floor
    j = min(max(j, 0), TAB_N - 1);
    float fr = t - (float)j;
    float2 k0 = __ldg(&g_table[j]);
    float2 k1 = __ldg(&g_table[j + 1]);
    th = fmaf(fr, k1.x - k0.x, k0.x);
    acc += fmaf(fr, k1.y - k0.y, k0.y);
}

__global__ void __launch_bounds__(K2_THREADS)
lookup_kernel(const float* __restrict__ x, float* __restrict__ out)
{
    const int bidx  = blockIdx.x;
    const int row   = bidx / CHUNKS;
    const int chunk = bidx % CHUNKS;
    const int base4 = (row * P_DIM + chunk * (P_DIM / CHUNKS)) >> 2;

    const float4* x4 = reinterpret_cast<const float4*>(x) + base4;
    float4*       o4 = reinterpret_cast<float4*>(out) + base4;

    float acc = 0.0f;
#pragma unroll
    for (int k = 0; k < K2_VECS; k++) {
        int vi = threadIdx.x + k * K2_THREADS;
        float4 xv = x4[vi];
        float4 th;
        lut_eval(xv.x, th.x, acc);
        lut_eval(xv.y, th.y, acc);
        lut_eval(xv.z, th.z, acc);
        lut_eval(xv.w, th.w, acc);
        o4[vi] = th;
    }

    // deterministic intra-block reduction of act
#pragma unroll
    for (int off = 16; off > 0; off >>= 1)
        acc += __shfl_down_sync(0xffffffffu, acc, off);

    __shared__ float ws[K2_THREADS / 32];
    if ((threadIdx.x & 31) == 0) ws[threadIdx.x >> 5] = acc;
    __syncthreads();
    if (threadIdx.x == 0) {
        float s = 0.0f;
#pragma unroll
        for (int w = 0; w < K2_THREADS / 32; w++) s += ws[w];
        g_partial[bidx] = s;
    }
}

// ----------------------------------------------------------------------------
// Kernel 3: qt[b] = (sum of CHUNKS partials) / P
// ----------------------------------------------------------------------------
__global__ void finalize_kernel(float* __restrict__ out)
{
    int b = threadIdx.x;
    if (b >= B_DIM) return;
    float s = 0.0f;
#pragma unroll
    for (int c = 0; c < CHUNKS; c++) s += g_partial[b * CHUNKS + c];
    out[B_DIM * P_DIM + b] = s * (1.0f / (float)P_DIM);
}

// ----------------------------------------------------------------------------
extern "C" void kernel_launch(void* const* d_in, const int* in_sizes, int n_in,
                              void* d_out, int out_size)
{
    const float* x     = (const float*)d_in[0];
    const float* W1    = (const float*)d_in[1];
    const float* b1    = (const float*)d_in[2];
    const float* W_ih  = (const float*)d_in[3];
    const float* b_ih  = (const float*)d_in[4];
    // d_in[5] = W_hh (unused: h0 = 0)
    const float* b_hh  = (const float*)d_in[6];
    const float* W_out = (const float*)d_in[7];
    const float* b_out = (const float*)d_in[8];
    const float* W_act = (const float*)d_in[9];
    const float* b_act = (const float*)d_in[10];

    float* out = (float*)d_out;

    build_table_kernel<<<(TAB_N + 1 + 255) / 256, 256>>>(
        W1, b1, W_ih, b_ih, b_hh, W_out, b_out, W_act, b_act);

    lookup_kernel<<<B_DIM * CHUNKS, K2_THREADS>>>(x, out);

    finalize_kernel<<<1, B_DIM>>>(out);
}